// round 13
// baseline (speedup 1.0000x reference)
#include <cuda_runtime.h>
#include <cuda_fp16.h>
#include <cstdint>
#include <math.h>

// ---------------------------------------------------------------------------
// GroupedGLU, fused single-kernel fp16 HMMA (fp32 accumulate).
// R13: R12 + cp.async group-accounting FIX: the final iteration of each phase
// loop must use wait_group 0 (WAIT1 is a no-op when exactly 1 group pends --
// this was the "race": the last B/wd tile was read before arrival).
// Each CTA owns 64 tokens: phase1 x@Wg/Wu -> h (L2-hot), phase2 h@Wd -> y.
// ---------------------------------------------------------------------------

#define T_TOK   131072
#define DMODEL  256
#define DFF_    1024
#define NG      8
#define TPG     (T_TOK / NG)
#define SAB     144           // smem row stride bytes (72 fp16: 64 data + 8 pad)

__device__ __half g_x[(size_t)T_TOK * DMODEL];
__device__ __half g_h[(size_t)T_TOK * DFF_];
__device__ __half g_wg[(size_t)NG * DFF_ * DMODEL];
__device__ __half g_wu[(size_t)NG * DFF_ * DMODEL];
__device__ __half g_wd[(size_t)NG * DMODEL * DFF_];

// ------------------------------- helpers -----------------------------------

__device__ __forceinline__ uint32_t smaddr(const void* p) {
    return (uint32_t)__cvta_generic_to_shared(p);
}

__device__ __forceinline__ void cp16(uint32_t dst, const void* src) {
    asm volatile("cp.async.cg.shared.global [%0], [%1], 16;" :: "r"(dst), "l"(src));
}
#define CP_COMMIT() asm volatile("cp.async.commit_group;" ::: "memory")
#define CP_WAIT1()  asm volatile("cp.async.wait_group 1;" ::: "memory")
#define CP_WAIT0()  asm volatile("cp.async.wait_group 0;" ::: "memory")

__device__ __forceinline__ void ldm_x4(uint32_t addr, uint32_t* r) {
    asm volatile("ldmatrix.sync.aligned.m8n8.x4.shared.b16 {%0,%1,%2,%3}, [%4];"
        : "=r"(r[0]), "=r"(r[1]), "=r"(r[2]), "=r"(r[3]) : "r"(addr));
}

__device__ __forceinline__ void mma16816(float* c, const uint32_t* a,
                                         uint32_t b0, uint32_t b1) {
    asm volatile(
        "mma.sync.aligned.m16n8k16.row.col.f32.f16.f16.f32 "
        "{%0,%1,%2,%3}, {%4,%5,%6,%7}, {%8,%9}, {%0,%1,%2,%3};"
        : "+f"(c[0]), "+f"(c[1]), "+f"(c[2]), "+f"(c[3])
        : "r"(a[0]), "r"(a[1]), "r"(a[2]), "r"(a[3]), "r"(b0), "r"(b1));
}

__device__ __forceinline__ void stg_cg(void* p, uint32_t v) {
    asm volatile("st.global.cg.u32 [%0], %1;" :: "l"(p), "r"(v) : "memory");
}

__device__ __forceinline__ uint32_t pack2h(float vx, float vy) {
    __half hx = __float2half_rn(vx);
    __half hy = __float2half_rn(vy);
    return ((uint32_t)__half_as_ushort(hy) << 16) | (uint32_t)__half_as_ushort(hx);
}

__device__ __forceinline__ float silu_f(float z) {
    return z / (1.0f + __expf(-z));
}

// ----------------------------- prep kernel ---------------------------------
#define W_BLOCKS 6144
#define X_BLOCKS 16384

__global__ void __launch_bounds__(256) prep_kernel(
    const float* __restrict__ x, const float* __restrict__ wg,
    const float* __restrict__ wu, const float* __restrict__ wd) {
    __shared__ float tile[32][33];
    const int bid = blockIdx.x;
    const int tid = threadIdx.x;

    if (bid >= W_BLOCKS) {
        size_t e0 = ((size_t)(bid - W_BLOCKS) * 256 + tid) * 8;
        #pragma unroll
        for (int j = 0; j < 2; j++) {
            float4 v = *(const float4*)&x[e0 + j * 4];
            *(uint2*)&g_x[e0 + j * 4] =
                make_uint2(pack2h(v.x, v.y), pack2h(v.z, v.w));
        }
        return;
    }

    const int which = bid / 2048;
    const int rem = bid % 2048;
    const int g = rem >> 8;
    const int t = rem & 255;
    int R, C;
    const float* in;
    __half* dh0;
    if (which == 0)      { R = DMODEL; C = DFF_;  in = wg; dh0 = g_wg; }
    else if (which == 1) { R = DMODEL; C = DFF_;  in = wu; dh0 = g_wu; }
    else                 { R = DFF_;  C = DMODEL; in = wd; dh0 = g_wd; }
    const int tilesC = C / 32;
    const int c0 = (t % tilesC) * 32, r0 = (t / tilesC) * 32;
    const float* src = in + (size_t)g * R * C;
    __half* dh = dh0 + (size_t)g * R * C;
    const int tx = tid & 31, ty = tid >> 5;
    #pragma unroll
    for (int j = ty; j < 32; j += 8)
        tile[j][tx] = src[(size_t)(r0 + j) * C + c0 + tx];
    __syncthreads();
    #pragma unroll
    for (int j = ty; j < 32; j += 8) {
        float v = tile[tx][j];
        dh[(size_t)(c0 + j) * R + r0 + tx] = __float2half_rn(v);
    }
}

// ----------------------------- fused kernel --------------------------------
// CTA = 64 tokens. smem:
//   phase1: A resident 4 chunks x 9216 @ 0; B ring 3 x 18432 @ 36864 (Bg+Bu)
//   phase2: ring 3 x 27648 @ 0 (h 9216 + wd 18432)
// total 92160 B; 2 CTA/SM.
#define F_A      0u
#define F_BRING  36864u
#define F_BSTG   18432u
#define F_STG2   27648u
#define F_SMEM   92160

__global__ void __launch_bounds__(256, 2) fused_kernel(float* __restrict__ out) {
    extern __shared__ __align__(16) char sm[];
    const uint32_t sbase = smaddr(sm);
    const int tid  = threadIdx.x;
    const int lane = tid & 31, w = tid >> 5;
    const int wm = w & 1, wn = w >> 1;          // 2(M) x 4(N) warps
    const int gID = lane >> 2, tig = lane & 3;
    const int m0 = blockIdx.x * 64;
    const int g  = m0 / TPG;

    const __half* wgp = g_wg + (size_t)g * DFF_ * DMODEL;
    const __half* wup = g_wu + (size_t)g * DFF_ * DMODEL;
    const __half* wdp = g_wd + (size_t)g * DMODEL * DFF_;

    // ldmatrix lane offsets (bytes) — verified mappings
    const uint32_t a_off  = (uint32_t)(wm * 32 + (lane & 15)) * SAB + ((lane >> 4) << 4);
    const uint32_t b1_off = (uint32_t)(wn * 16 + (lane & 7) + ((lane >> 4) << 3)) * SAB
                          + (((lane >> 3) & 1) << 4);
    const uint32_t b2_off = (uint32_t)(wn * 32 + (lane & 7) + ((lane >> 4) << 3)) * SAB
                          + (((lane >> 3) & 1) << 4);

    // ========================== PHASE 1: gate/up ==========================
    {
        // load resident A: 4 chunks x (64 rows x 8 segs)
        #pragma unroll
        for (int i = 0; i < 8; i++) {
            int t = tid + i * 256;
            int c = t >> 9, r = (t >> 3) & 63, s = t & 7;
            cp16(sbase + F_A + (uint32_t)c * 9216u + (uint32_t)r * SAB + (uint32_t)s * 16,
                 g_x + (size_t)(m0 + r) * DMODEL + c * 64 + s * 8);
        }
        CP_COMMIT();

        auto issueB = [&](int ci) {
            const uint32_t sb = sbase + F_BRING + (uint32_t)(ci % 3) * F_BSTG;
            const int nb = ci >> 2, kc = ci & 3;
            #pragma unroll
            for (int i = 0; i < 2; i++) {
                int t = tid + i * 256;
                int row = t >> 3, seg = t & 7;
                size_t so = (size_t)(nb * 64 + row) * DMODEL + kc * 64 + seg * 8;
                uint32_t d = sb + (uint32_t)row * SAB + (uint32_t)seg * 16;
                cp16(d,         wgp + so);
                cp16(d + 9216u, wup + so);
            }
        };

        issueB(0); CP_COMMIT();
        issueB(1); CP_COMMIT();

        float cg[2][2][4] = {}, cu[2][2][4] = {};

        #pragma unroll 1
        for (int ci = 0; ci < 64; ci++) {
            const int nb = ci >> 2, kc = ci & 3;
            if (ci < 63) CP_WAIT1();   // FIX: last iter must fully drain
            else         CP_WAIT0();
            __syncthreads();
            const uint32_t sa = sbase + F_A + (uint32_t)kc * 9216u;
            const uint32_t sb = sbase + F_BRING + (uint32_t)(ci % 3) * F_BSTG;
            #pragma unroll
            for (int k16 = 0; k16 < 4; k16++) {
                const uint32_t kb = (uint32_t)k16 * 32;
                uint32_t af[2][4], bg[4], bu[4];
                #pragma unroll
                for (int mf = 0; mf < 2; mf++)
                    ldm_x4(sa + a_off + (uint32_t)mf * (16 * SAB) + kb, af[mf]);
                ldm_x4(sb + b1_off + kb, bg);
                ldm_x4(sb + 9216u + b1_off + kb, bu);
                #pragma unroll
                for (int s = 0; s < 2; s++)
                    #pragma unroll
                    for (int mf = 0; mf < 2; mf++) {
                        mma16816(cg[mf][s], af[mf], bg[2*s], bg[2*s+1]);
                        mma16816(cu[mf][s], af[mf], bu[2*s], bu[2*s+1]);
                    }
            }
            if (ci + 2 < 64) { issueB(ci + 2); CP_COMMIT(); }
            if (kc == 3) {
                // epilogue: h = silu(zg)*zu for this nb  -> L2 via st.global.cg
                #pragma unroll
                for (int mf = 0; mf < 2; mf++)
                    #pragma unroll
                    for (int s = 0; s < 2; s++) {
                        int r0 = m0 + wm * 32 + mf * 16 + gID;
                        int c0 = nb * 64 + wn * 16 + s * 8 + tig * 2;
                        float h0 = silu_f(cg[mf][s][0]) * cu[mf][s][0];
                        float h1 = silu_f(cg[mf][s][1]) * cu[mf][s][1];
                        float h2 = silu_f(cg[mf][s][2]) * cu[mf][s][2];
                        float h3 = silu_f(cg[mf][s][3]) * cu[mf][s][3];
                        stg_cg(&g_h[(size_t)r0 * DFF_ + c0],       pack2h(h0, h1));
                        stg_cg(&g_h[(size_t)(r0 + 8) * DFF_ + c0], pack2h(h2, h3));
                        #pragma unroll
                        for (int q = 0; q < 4; q++) { cg[mf][s][q] = 0.f; cu[mf][s][q] = 0.f; }
                    }
            }
        }
        __threadfence();   // drain h stores to L2
        __syncthreads();   // cross-thread ordering; smem free for phase 2
    }

    // ============================ PHASE 2: down ============================
    // h staged SYNCHRONOUSLY: ld.global.cg -> regs (prefetch) -> st.shared.
    {
        auto ldg_h = [&](int ci, uint4* hv) {
            const int kc = ci & 15;
            #pragma unroll
            for (int i = 0; i < 2; i++) {
                int t = tid + i * 256;
                int row = t >> 3, seg = t & 7;
                const __half* p = g_h + (size_t)(m0 + row) * DFF_ + kc * 64 + seg * 8;
                asm volatile("ld.global.cg.v4.u32 {%0,%1,%2,%3}, [%4];"
                    : "=r"(hv[i].x), "=r"(hv[i].y), "=r"(hv[i].z), "=r"(hv[i].w)
                    : "l"(p));
            }
        };
        auto sts_h = [&](int ci, const uint4* hv) {
            const uint32_t sb = sbase + (uint32_t)(ci % 3) * F_STG2;
            #pragma unroll
            for (int i = 0; i < 2; i++) {
                int t = tid + i * 256;
                int row = t >> 3, seg = t & 7;
                asm volatile("st.shared.v4.u32 [%0], {%1,%2,%3,%4};"
                    :: "r"(sb + (uint32_t)row * SAB + (uint32_t)seg * 16),
                       "r"(hv[i].x), "r"(hv[i].y), "r"(hv[i].z), "r"(hv[i].w)
                    : "memory");
            }
        };
        auto issue_wd = [&](int ci) {
            const uint32_t sb = sbase + (uint32_t)(ci % 3) * F_STG2;
            const int nh = ci >> 4, kc = ci & 15;
            #pragma unroll
            for (int i = 0; i < 4; i++) {
                int t = tid + i * 256;
                int row = t >> 3, seg = t & 7;
                cp16(sb + 9216u + (uint32_t)row * SAB + (uint32_t)seg * 16,
                     wdp + (size_t)(nh * 128 + row) * DFF_ + kc * 64 + seg * 8);
            }
        };

        // prolog: stage slots 0,1
        {
            uint4 h0[2], h1[2];
            ldg_h(0, h0); ldg_h(1, h1);
            sts_h(0, h0); sts_h(1, h1);
            issue_wd(0); CP_COMMIT();
            issue_wd(1); CP_COMMIT();
        }

        float c[2][4][4] = {};

        #pragma unroll 1
        for (int ci = 0; ci < 32; ci++) {
            const int nh = ci >> 4, kc = ci & 15;
            if (ci < 31) CP_WAIT1();   // FIX: last iter must fully drain
            else         CP_WAIT0();
            __syncthreads();
            uint4 hnext[2];
            if (ci + 2 < 32) ldg_h(ci + 2, hnext);   // prefetch h (latency hidden)
            const uint32_t sb = sbase + (uint32_t)(ci % 3) * F_STG2;
            #pragma unroll
            for (int k16 = 0; k16 < 4; k16++) {
                const uint32_t kb = (uint32_t)k16 * 32;
                uint32_t af[2][4], bf[2][4];
                #pragma unroll
                for (int mf = 0; mf < 2; mf++)
                    ldm_x4(sb + a_off + (uint32_t)mf * (16 * SAB) + kb, af[mf]);
                #pragma unroll
                for (int p = 0; p < 2; p++)
                    ldm_x4(sb + 9216u + b2_off + (uint32_t)p * (16 * SAB) + kb, bf[p]);
                #pragma unroll
                for (int p = 0; p < 2; p++)
                    #pragma unroll
                    for (int s = 0; s < 2; s++)
                        #pragma unroll
                        for (int mf = 0; mf < 2; mf++)
                            mma16816(c[mf][p*2+s], af[mf], bf[p][2*s], bf[p][2*s+1]);
            }
            if (ci + 2 < 32) {
                sts_h(ci + 2, hnext);                // slot (ci+2)%3: safe post-sync
                issue_wd(ci + 2); CP_COMMIT();
            }
            if (kc == 15) {
                #pragma unroll
                for (int mf = 0; mf < 2; mf++)
                    #pragma unroll
                    for (int nf = 0; nf < 4; nf++) {
                        int r0 = m0 + wm * 32 + mf * 16 + gID;
                        int c0 = nh * 128 + wn * 32 + nf * 8 + tig * 2;
                        float2 v0 = { c[mf][nf][0], c[mf][nf][1] };
                        float2 v1 = { c[mf][nf][2], c[mf][nf][3] };
                        *(float2*)&out[(size_t)r0 * DMODEL + c0] = v0;
                        *(float2*)&out[(size_t)(r0 + 8) * DMODEL + c0] = v1;
                        #pragma unroll
                        for (int q = 0; q < 4; q++) c[mf][nf][q] = 0.f;
                    }
            }
        }
    }
}

// ------------------------------- launch -------------------------------------
extern "C" void kernel_launch(void* const* d_in, const int* in_sizes, int n_in,
                              void* d_out, int out_size) {
    const float* x  = (const float*)d_in[0];
    const float* wg = (const float*)d_in[1];
    const float* wu = (const float*)d_in[2];
    const float* wd = (const float*)d_in[3];
    // d_in[4] = offs: uniform groups by construction (reference reshapes by T/G)

    cudaFuncSetAttribute(fused_kernel, cudaFuncAttributeMaxDynamicSharedMemorySize, F_SMEM);

    prep_kernel<<<W_BLOCKS + X_BLOCKS, 256>>>(x, wg, wu, wd);
    fused_kernel<<<T_TOK / 64, 256, F_SMEM>>>((float*)d_out);
}

// round 14
// speedup vs baseline: 1.1812x; 1.1812x over previous
#include <cuda_runtime.h>
#include <cuda_fp16.h>
#include <cstdint>
#include <math.h>

// ---------------------------------------------------------------------------
// GroupedGLU via mma.sync (HMMA) single-pass fp16 GEMMs (fp32 accumulate).
// R14: revert to R9 (best: 637.7us) — fusion abandoned (profile showed
// DRAM=7.6%: the h round-trip was already hidden; fused M=64 tile lowered
// tensor util). Adds #pragma unroll 2 on the K-chunk loops for cross-
// iteration scheduling.
//   prep:   x fp32 -> fp16 ; W fp32 [R][C] -> W^T fp16 [C][R]
//   gemm1:  z_gate,z_up = x @ Wg, x @ Wu ; h = silu(zg)*zu -> fp16
//   gemm2:  y = h @ Wd -> fp32 out
// ---------------------------------------------------------------------------

#define T_TOK   131072
#define DMODEL  256
#define DFF_    1024
#define NG      8
#define TPG     (T_TOK / NG)
#define SAB     144           // smem row stride bytes (72 fp16: 64 data + 8 pad)

__device__ __half g_x[(size_t)T_TOK * DMODEL];
__device__ __half g_h[(size_t)T_TOK * DFF_];
__device__ __half g_wg[(size_t)NG * DFF_ * DMODEL];
__device__ __half g_wu[(size_t)NG * DFF_ * DMODEL];
__device__ __half g_wd[(size_t)NG * DMODEL * DFF_];

// ------------------------------- helpers -----------------------------------

__device__ __forceinline__ uint32_t smaddr(const void* p) {
    return (uint32_t)__cvta_generic_to_shared(p);
}

__device__ __forceinline__ void cp16(uint32_t dst, const void* src) {
    asm volatile("cp.async.cg.shared.global [%0], [%1], 16;" :: "r"(dst), "l"(src));
}
#define CP_COMMIT() asm volatile("cp.async.commit_group;" ::: "memory")
#define CP_WAIT1()  asm volatile("cp.async.wait_group 1;" ::: "memory")
#define CP_WAIT0()  asm volatile("cp.async.wait_group 0;" ::: "memory")

__device__ __forceinline__ void ldm_x4(uint32_t addr, uint32_t* r) {
    asm volatile("ldmatrix.sync.aligned.m8n8.x4.shared.b16 {%0,%1,%2,%3}, [%4];"
        : "=r"(r[0]), "=r"(r[1]), "=r"(r[2]), "=r"(r[3]) : "r"(addr));
}

__device__ __forceinline__ void mma16816(float* c, const uint32_t* a,
                                         uint32_t b0, uint32_t b1) {
    asm volatile(
        "mma.sync.aligned.m16n8k16.row.col.f32.f16.f16.f32 "
        "{%0,%1,%2,%3}, {%4,%5,%6,%7}, {%8,%9}, {%0,%1,%2,%3};"
        : "+f"(c[0]), "+f"(c[1]), "+f"(c[2]), "+f"(c[3])
        : "r"(a[0]), "r"(a[1]), "r"(a[2]), "r"(a[3]), "r"(b0), "r"(b1));
}

__device__ __forceinline__ uint32_t pack2h(float vx, float vy) {
    __half hx = __float2half_rn(vx);
    __half hy = __float2half_rn(vy);
    return ((uint32_t)__half_as_ushort(hy) << 16) | (uint32_t)__half_as_ushort(hx);
}

__device__ __forceinline__ float silu_f(float z) {
    return z / (1.0f + __expf(-z));
}

// ----------------------------- prep kernel ---------------------------------
#define W_BLOCKS 6144
#define X_BLOCKS 16384

__global__ void __launch_bounds__(256) prep_kernel(
    const float* __restrict__ x, const float* __restrict__ wg,
    const float* __restrict__ wu, const float* __restrict__ wd) {
    __shared__ float tile[32][33];
    const int bid = blockIdx.x;
    const int tid = threadIdx.x;

    if (bid >= W_BLOCKS) {
        size_t e0 = ((size_t)(bid - W_BLOCKS) * 256 + tid) * 8;
        #pragma unroll
        for (int j = 0; j < 2; j++) {
            float4 v = *(const float4*)&x[e0 + j * 4];
            *(uint2*)&g_x[e0 + j * 4] =
                make_uint2(pack2h(v.x, v.y), pack2h(v.z, v.w));
        }
        return;
    }

    const int which = bid / 2048;
    const int rem = bid % 2048;
    const int g = rem >> 8;
    const int t = rem & 255;
    int R, C;
    const float* in;
    __half* dh0;
    if (which == 0)      { R = DMODEL; C = DFF_;  in = wg; dh0 = g_wg; }
    else if (which == 1) { R = DMODEL; C = DFF_;  in = wu; dh0 = g_wu; }
    else                 { R = DFF_;  C = DMODEL; in = wd; dh0 = g_wd; }
    const int tilesC = C / 32;
    const int c0 = (t % tilesC) * 32, r0 = (t / tilesC) * 32;
    const float* src = in + (size_t)g * R * C;
    __half* dh = dh0 + (size_t)g * R * C;
    const int tx = tid & 31, ty = tid >> 5;
    #pragma unroll
    for (int j = ty; j < 32; j += 8)
        tile[j][tx] = src[(size_t)(r0 + j) * C + c0 + tx];
    __syncthreads();
    #pragma unroll
    for (int j = ty; j < 32; j += 8) {
        float v = tile[tx][j];
        dh[(size_t)(c0 + j) * R + r0 + tx] = __float2half_rn(v);
    }
}

// --------------------------- GEMM1: gate/up --------------------------------
// block 128 tok x 64 dff (gate AND up), K=256 in 4 chunks of 64.
// 8 warps = 4(M) x 2(N). Stage bytes: A 0 (128*144=18432), Bg 18432,
// Bu 27648; stage 36864; 3-stage ring = 110592. 2 CTA/SM.
#define G1_A    0u
#define G1_BG   18432u
#define G1_BU   27648u
#define G1_STG  36864u
#define G1_SMEM (3 * 36864)

__global__ void __launch_bounds__(256, 2) gemm1_kernel() {
    extern __shared__ __align__(16) char sm[];
    const uint32_t sbase = smaddr(sm);
    const int tid  = threadIdx.x;
    const int lane = tid & 31, w = tid >> 5;
    const int wm = w & 3, wn = w >> 2;
    const int gID = lane >> 2, tig = lane & 3;
    const int m0 = blockIdx.y * 128;
    const int n0 = blockIdx.x * 64;
    const int g  = m0 / TPG;

    const __half* wgp = g_wg + ((size_t)g * DFF_ + n0) * DMODEL;
    const __half* wup = g_wu + ((size_t)g * DFF_ + n0) * DMODEL;

    const uint32_t a_off = (uint32_t)(wm * 32 + (lane & 15)) * SAB + ((lane >> 4) << 4);
    const uint32_t b_off = (uint32_t)(wn * 32 + (lane & 7) + ((lane >> 4) << 3)) * SAB
                         + (((lane >> 3) & 1) << 4);
    const int arow = tid >> 3, aseg = tid & 7;

    float cg[2][4][4] = {}, cu[2][4][4] = {};

    auto issue = [&](int kc) {
        const uint32_t sb = sbase + (uint32_t)(kc % 3) * G1_STG;
        const int k0g = kc * 64;
        #pragma unroll
        for (int t = 0; t < 4; t++) {
            int row = arow + t * 32;
            size_t so = (size_t)(m0 + row) * DMODEL + k0g + aseg * 8;
            uint32_t d = sb + (uint32_t)row * SAB + (uint32_t)aseg * 16;
            cp16(d + G1_A, g_x + so);
        }
        #pragma unroll
        for (int t = 0; t < 2; t++) {
            int row = arow + t * 32;
            size_t so = (size_t)row * DMODEL + k0g + aseg * 8;
            uint32_t d = sb + (uint32_t)row * SAB + (uint32_t)aseg * 16;
            cp16(d + G1_BG, wgp + so);
            cp16(d + G1_BU, wup + so);
        }
    };

    auto compute = [&](int kc) {
        const uint32_t sb = sbase + (uint32_t)(kc % 3) * G1_STG;
        #pragma unroll
        for (int k16 = 0; k16 < 4; k16++) {
            const uint32_t kb = (uint32_t)k16 * 32;
            uint32_t af[2][4];
            uint32_t bg[2][4], bu[2][4];
            #pragma unroll
            for (int mf = 0; mf < 2; mf++)
                ldm_x4(sb + G1_A + a_off + (uint32_t)mf * (16 * SAB) + kb, af[mf]);
            #pragma unroll
            for (int p = 0; p < 2; p++) {
                uint32_t bo = b_off + (uint32_t)p * (16 * SAB) + kb;
                ldm_x4(sb + G1_BG + bo, bg[p]);
                ldm_x4(sb + G1_BU + bo, bu[p]);
            }
            #pragma unroll
            for (int p = 0; p < 2; p++)
                #pragma unroll
                for (int s = 0; s < 2; s++)
                    #pragma unroll
                    for (int mf = 0; mf < 2; mf++) {
                        mma16816(cg[mf][p*2+s], af[mf], bg[p][2*s], bg[p][2*s+1]);
                        mma16816(cu[mf][p*2+s], af[mf], bu[p][2*s], bu[p][2*s+1]);
                    }
        }
    };

    issue(0); CP_COMMIT();
    issue(1); CP_COMMIT();
    #pragma unroll 2
    for (int kc = 0; kc < 4; kc++) {
        if (kc < 3) CP_WAIT1();
        else        CP_WAIT0();
        __syncthreads();
        compute(kc);
        if (kc + 2 < 4) { issue(kc + 2); CP_COMMIT(); }
    }

    #pragma unroll
    for (int mf = 0; mf < 2; mf++) {
        #pragma unroll
        for (int nf = 0; nf < 4; nf++) {
            int r0 = m0 + wm * 32 + mf * 16 + gID;
            int c0 = n0 + wn * 32 + nf * 8 + tig * 2;
            float h0 = silu_f(cg[mf][nf][0]) * cu[mf][nf][0];
            float h1 = silu_f(cg[mf][nf][1]) * cu[mf][nf][1];
            float h2 = silu_f(cg[mf][nf][2]) * cu[mf][nf][2];
            float h3 = silu_f(cg[mf][nf][3]) * cu[mf][nf][3];
            *(uint32_t*)&g_h[(size_t)r0 * DFF_ + c0]       = pack2h(h0, h1);
            *(uint32_t*)&g_h[(size_t)(r0 + 8) * DFF_ + c0] = pack2h(h2, h3);
        }
    }
}

// ----------------------------- GEMM2: down ---------------------------------
// block 128 tok x 128 dmodel, K=1024 in 16 chunks of 64.
// 8 warps = 4(M) x 2(N), warp N=64. Stage bytes: A 0, B 18432;
// stage 36864; 3-stage ring = 110592. 2 CTA/SM.
#define G2_A    0u
#define G2_B    18432u
#define G2_STG  36864u
#define G2_SMEM (3 * 36864)

__global__ void __launch_bounds__(256, 2) gemm2_kernel(float* __restrict__ out) {
    extern __shared__ __align__(16) char sm[];
    const uint32_t sbase = smaddr(sm);
    const int tid  = threadIdx.x;
    const int lane = tid & 31, w = tid >> 5;
    const int wm = w & 3, wn = w >> 2;
    const int gID = lane >> 2, tig = lane & 3;
    const int m0 = blockIdx.y * 128;
    const int n0 = blockIdx.x * 128;
    const int g  = m0 / TPG;

    const __half* wdp = g_wd + ((size_t)g * DMODEL + n0) * DFF_;

    const uint32_t a_off = (uint32_t)(wm * 32 + (lane & 15)) * SAB + ((lane >> 4) << 4);
    const uint32_t b_off = (uint32_t)(wn * 64 + (lane & 7) + ((lane >> 4) << 3)) * SAB
                         + (((lane >> 3) & 1) << 4);
    const int arow = tid >> 3, aseg = tid & 7;

    float c[2][8][4] = {};

    auto issue = [&](int kc) {
        const uint32_t sb = sbase + (uint32_t)(kc % 3) * G2_STG;
        const int k0g = kc * 64;
        #pragma unroll
        for (int t = 0; t < 4; t++) {
            int row = arow + t * 32;
            size_t soA = (size_t)(m0 + row) * DFF_ + k0g + aseg * 8;
            size_t soB = (size_t)row * DFF_ + k0g + aseg * 8;
            uint32_t d = sb + (uint32_t)row * SAB + (uint32_t)aseg * 16;
            cp16(d + G2_A, g_h + soA);
            cp16(d + G2_B, wdp + soB);
        }
    };

    auto compute = [&](int kc) {
        const uint32_t sb = sbase + (uint32_t)(kc % 3) * G2_STG;
        #pragma unroll
        for (int k16 = 0; k16 < 4; k16++) {
            const uint32_t kb = (uint32_t)k16 * 32;
            uint32_t af[2][4];
            uint32_t bf[4][4];
            #pragma unroll
            for (int mf = 0; mf < 2; mf++)
                ldm_x4(sb + G2_A + a_off + (uint32_t)mf * (16 * SAB) + kb, af[mf]);
            #pragma unroll
            for (int p = 0; p < 4; p++) {
                uint32_t bo = b_off + (uint32_t)p * (16 * SAB) + kb;
                ldm_x4(sb + G2_B + bo, bf[p]);
            }
            #pragma unroll
            for (int p = 0; p < 4; p++)
                #pragma unroll
                for (int s = 0; s < 2; s++)
                    #pragma unroll
                    for (int mf = 0; mf < 2; mf++)
                        mma16816(c[mf][p*2+s], af[mf], bf[p][2*s], bf[p][2*s+1]);
        }
    };

    issue(0); CP_COMMIT();
    issue(1); CP_COMMIT();
    #pragma unroll 2
    for (int kc = 0; kc < 16; kc++) {
        if (kc < 15) CP_WAIT1();
        else         CP_WAIT0();
        __syncthreads();
        compute(kc);
        if (kc + 2 < 16) { issue(kc + 2); CP_COMMIT(); }
    }

    #pragma unroll
    for (int mf = 0; mf < 2; mf++) {
        #pragma unroll
        for (int nf = 0; nf < 8; nf++) {
            int r0 = m0 + wm * 32 + mf * 16 + gID;
            int c0 = n0 + wn * 64 + nf * 8 + tig * 2;
            float2 v0 = { c[mf][nf][0], c[mf][nf][1] };
            float2 v1 = { c[mf][nf][2], c[mf][nf][3] };
            *(float2*)&out[(size_t)r0 * DMODEL + c0] = v0;
            *(float2*)&out[(size_t)(r0 + 8) * DMODEL + c0] = v1;
        }
    }
}

// ------------------------------- launch -------------------------------------
extern "C" void kernel_launch(void* const* d_in, const int* in_sizes, int n_in,
                              void* d_out, int out_size) {
    const float* x  = (const float*)d_in[0];
    const float* wg = (const float*)d_in[1];
    const float* wu = (const float*)d_in[2];
    const float* wd = (const float*)d_in[3];
    // d_in[4] = offs: uniform groups by construction (reference reshapes by T/G)

    cudaFuncSetAttribute(gemm1_kernel, cudaFuncAttributeMaxDynamicSharedMemorySize, G1_SMEM);
    cudaFuncSetAttribute(gemm2_kernel, cudaFuncAttributeMaxDynamicSharedMemorySize, G2_SMEM);

    prep_kernel<<<W_BLOCKS + X_BLOCKS, 256>>>(x, wg, wu, wd);
    gemm1_kernel<<<dim3(DFF_ / 64, T_TOK / 128), 256, G1_SMEM>>>();
    gemm2_kernel<<<dim3(DMODEL / 128, T_TOK / 128), 256, G2_SMEM>>>((float*)d_out);
}